// round 3
// baseline (speedup 1.0000x reference)
#include <cuda_runtime.h>
#include <cuda_fp16.h>

#define PHp 7
#define PWp 7
#define SRs 2
#define SCALEc 0.0625f
#define Bc 2
#define Cc 256
#define Hc 100
#define Wc 152
#define Rc 1024
#define HWc (Hc * Wc)          // 15200

// NHWC fp16 scratch: [B][H*W][C] halfs = 15.6 MB
__device__ __half g_nhwc[(size_t)Bc * HWc * Cc];

// ---------------- Phase 1: NCHW fp32 -> NHWC fp16 ----------------
__global__ void __launch_bounds__(256) transpose_kernel(const float* __restrict__ in)
{
    __shared__ float tile[32][33];
    int s0 = blockIdx.x * 32;           // HW tile (475 exact)
    int c0 = blockIdx.y * 32;           // C tile (8 exact)
    int b  = blockIdx.z;

    const float* ib = in + (size_t)b * Cc * HWc;
    __half* ob = g_nhwc + (size_t)b * HWc * Cc;

    int s = s0 + threadIdx.x;
    #pragma unroll
    for (int j = threadIdx.y; j < 32; j += 8)
        tile[j][threadIdx.x] = ib[(size_t)(c0 + j) * HWc + s];
    __syncthreads();

    int c = c0 + threadIdx.x;
    #pragma unroll
    for (int j = threadIdx.y; j < 32; j += 8)
        ob[(size_t)(s0 + j) * Cc + c] = __float2half_rn(tile[threadIdx.x][j]);
}

// ---------------- Phase 2: RoIAlign on NHWC fp16 ----------------
// One block per (roi, channel-half). 256 threads:
//   c8 = tid & 15  -> 16-byte channel group (16 groups * 8 ch = 128 channels)
//   bs = tid >> 4  -> 16 parallel bin streams over 49 bins
// Each corner load: 16 lanes * 16B = 256B contiguous (uint4 = 8 fp16 channels).
#define CPAD 132   // 128 + pad, keeps 16B alignment (132*4=528)

__global__ void __launch_bounds__(256) roialign_nhwc_kernel(
    const float* __restrict__ rois,
    float* __restrict__ out)
{
    __shared__ float s[PHp * PWp * CPAD];   // 25,872 B

    int r    = blockIdx.x >> 1;
    int half = blockIdx.x & 1;
    int tid  = threadIdx.x;
    int c8   = tid & 15;
    int bs   = tid >> 4;

    const float* roi = rois + r * 5;
    int   b   = (int)roi[0];
    float rsw = roi[1] * SCALEc;
    float rsh = roi[2] * SCALEc;
    float roi_w = fmaxf(roi[3] * SCALEc - rsw, 1.0f);
    float roi_h = fmaxf(roi[4] * SCALEc - rsh, 1.0f);
    float bin_h = roi_h * (1.0f / PHp);
    float bin_w = roi_w * (1.0f / PWp);

    const __half* fb = g_nhwc + (size_t)b * HWc * Cc + (half * 128 + c8 * 8);

    for (int bin = bs; bin < PHp * PWp; bin += 16) {
        int ph = bin / PWp;
        int pw = bin - ph * PWp;

        float a0=0.f,a1=0.f,a2=0.f,a3=0.f,a4=0.f,a5=0.f,a6=0.f,a7=0.f;

        #pragma unroll
        for (int iy = 0; iy < SRs; iy++) {
            float y = rsh + ((float)ph + ((float)iy + 0.5f) * (1.0f / SRs)) * bin_h;
            #pragma unroll
            for (int ix = 0; ix < SRs; ix++) {
                float x = rsw + ((float)pw + ((float)ix + 0.5f) * (1.0f / SRs)) * bin_w;

                bool valid = (y >= -1.0f) && (y <= (float)Hc) &&
                             (x >= -1.0f) && (x <= (float)Wc);
                if (!valid) continue;

                float yc = fminf(fmaxf(y, 0.0f), (float)(Hc - 1));
                float xc = fminf(fmaxf(x, 0.0f), (float)(Wc - 1));
                int ylo = (int)floorf(yc);
                int xlo = (int)floorf(xc);
                int yhi = min(ylo + 1, Hc - 1);
                int xhi = min(xlo + 1, Wc - 1);
                float ly = yc - (float)ylo;
                float lx = xc - (float)xlo;
                float hy = 1.0f - ly, hx = 1.0f - lx;
                float w11 = hy * hx, w12 = hy * lx;
                float w21 = ly * hx, w22 = ly * lx;

                const __half2* p11 = (const __half2*)(fb + (size_t)(ylo * Wc + xlo) * Cc);
                const __half2* p12 = (const __half2*)(fb + (size_t)(ylo * Wc + xhi) * Cc);
                const __half2* p21 = (const __half2*)(fb + (size_t)(yhi * Wc + xlo) * Cc);
                const __half2* p22 = (const __half2*)(fb + (size_t)(yhi * Wc + xhi) * Cc);

                // 16B vector loads (4 x half2 each)
                float2 f;
                #define ACC(P, W) { \
                    f = __half22float2(P[0]); a0 = fmaf(W, f.x, a0); a1 = fmaf(W, f.y, a1); \
                    f = __half22float2(P[1]); a2 = fmaf(W, f.x, a2); a3 = fmaf(W, f.y, a3); \
                    f = __half22float2(P[2]); a4 = fmaf(W, f.x, a4); a5 = fmaf(W, f.y, a5); \
                    f = __half22float2(P[3]); a6 = fmaf(W, f.x, a6); a7 = fmaf(W, f.y, a7); }
                ACC(p11, w11)
                ACC(p12, w12)
                ACC(p21, w21)
                ACC(p22, w22)
                #undef ACC
            }
        }

        float* sp = s + bin * CPAD + c8 * 8;
        float4 o0 = make_float4(a0*0.25f, a1*0.25f, a2*0.25f, a3*0.25f);
        float4 o1 = make_float4(a4*0.25f, a5*0.25f, a6*0.25f, a7*0.25f);
        *(float4*)(sp)     = o0;
        *(float4*)(sp + 4) = o1;
    }
    __syncthreads();

    // Coalesced copy-out: out[r][c][ph][pw]; this block's 128*49 floats contiguous.
    float* ob = out + (size_t)r * (Cc * PHp * PWp) + (size_t)half * 128 * PHp * PWp;
    #pragma unroll 4
    for (int i = tid; i < 128 * PHp * PWp; i += 256) {
        int c = i / (PHp * PWp);
        int bin = i - c * (PHp * PWp);
        ob[i] = s[bin * CPAD + c];
    }
}

extern "C" void kernel_launch(void* const* d_in, const int* in_sizes, int n_in,
                              void* d_out, int out_size)
{
    const float* feat = (const float*)d_in[0];
    const float* rois = (const float*)d_in[1];
    float* out = (float*)d_out;

    dim3 tg(HWc / 32, Cc / 32, Bc);        // 475 x 8 x 2
    dim3 tb(32, 8, 1);
    transpose_kernel<<<tg, tb>>>(feat);

    roialign_nhwc_kernel<<<Rc * 2, 256>>>(rois, out);
}

// round 4
// speedup vs baseline: 1.4173x; 1.4173x over previous
#include <cuda_runtime.h>
#include <cuda_fp16.h>

#define PHp 7
#define PWp 7
#define SRs 2
#define SCALEc 0.0625f
#define Bc 2
#define Cc 256
#define Hc 100
#define Wc 152
#define Rc 1024
#define HWc (Hc * Wc)          // 15200

// NHWC fp16 scratch: [B][H*W][C] halfs = 15.6 MB
__device__ __half g_nhwc[(size_t)Bc * HWc * Cc];

// ---------------- Phase 1: NCHW fp32 -> NHWC fp16 (half2 writes) ----------------
// Tile: 32 spatial x 64 channels. Write side: lane packs 2 channels -> half2,
// 32 lanes * 4B = 128B coalesced stores.
__global__ void __launch_bounds__(256) transpose_kernel(const float* __restrict__ in)
{
    __shared__ float tile[64][33];
    int s0 = blockIdx.x * 32;           // HW tile (475 exact)
    int c0 = blockIdx.y * 64;           // C tile (4 exact)
    int b  = blockIdx.z;

    const float* ib = in + (size_t)b * Cc * HWc;
    __half* ob = g_nhwc + (size_t)b * HWc * Cc;

    int s = s0 + threadIdx.x;
    #pragma unroll
    for (int j = threadIdx.y; j < 64; j += 8)
        tile[j][threadIdx.x] = ib[(size_t)(c0 + j) * HWc + s];
    __syncthreads();

    int tx = threadIdx.x;
    #pragma unroll
    for (int j = threadIdx.y; j < 32; j += 8) {
        __half2 v = __floats2half2_rn(tile[2 * tx][j], tile[2 * tx + 1][j]);
        *(__half2*)(ob + (size_t)(s0 + j) * Cc + c0 + 2 * tx) = v;
    }
}

// ---------------- Phase 2: RoIAlign on NHWC fp16 ----------------
// One block per (roi, channel-half). 256 threads:
//   c8 = tid & 15  -> lane's 8-channel group (16 lanes * 8 ch = 128 channels)
//   bs = tid >> 4  -> 16 parallel bin streams over 49 bins
// Each corner: ONE uint4 LDG.128 (16B = 8 fp16 channels), warp covers 2 bins.
#define CPAD 132   // 128 + 4 pad; bin stride 4 banks -> 4-way read conflict (ok)

__global__ void __launch_bounds__(256) roialign_nhwc_kernel(
    const float* __restrict__ rois,
    float* __restrict__ out)
{
    __shared__ float s[PHp * PWp * CPAD];   // 25,872 B

    int r    = blockIdx.x >> 1;
    int half = blockIdx.x & 1;
    int tid  = threadIdx.x;
    int c8   = tid & 15;
    int bs   = tid >> 4;

    const float* roi = rois + r * 5;
    int   b   = (int)roi[0];
    float rsw = roi[1] * SCALEc;
    float rsh = roi[2] * SCALEc;
    float roi_w = fmaxf(roi[3] * SCALEc - rsw, 1.0f);
    float roi_h = fmaxf(roi[4] * SCALEc - rsh, 1.0f);
    float bin_h = roi_h * (1.0f / PHp);
    float bin_w = roi_w * (1.0f / PWp);

    const __half* fb = g_nhwc + (size_t)b * HWc * Cc + (half * 128 + c8 * 8);

    for (int bin = bs; bin < PHp * PWp; bin += 16) {
        int ph = bin / PWp;
        int pw = bin - ph * PWp;

        float a0=0.f,a1=0.f,a2=0.f,a3=0.f,a4=0.f,a5=0.f,a6=0.f,a7=0.f;

        #pragma unroll
        for (int iy = 0; iy < SRs; iy++) {
            float y = rsh + ((float)ph + ((float)iy + 0.5f) * (1.0f / SRs)) * bin_h;
            #pragma unroll
            for (int ix = 0; ix < SRs; ix++) {
                float x = rsw + ((float)pw + ((float)ix + 0.5f) * (1.0f / SRs)) * bin_w;

                bool valid = (y >= -1.0f) && (y <= (float)Hc) &&
                             (x >= -1.0f) && (x <= (float)Wc);
                if (!valid) continue;

                float yc = fminf(fmaxf(y, 0.0f), (float)(Hc - 1));
                float xc = fminf(fmaxf(x, 0.0f), (float)(Wc - 1));
                int ylo = (int)floorf(yc);
                int xlo = (int)floorf(xc);
                int yhi = min(ylo + 1, Hc - 1);
                int xhi = min(xlo + 1, Wc - 1);
                float ly = yc - (float)ylo;
                float lx = xc - (float)xlo;
                float hy = 1.0f - ly, hx = 1.0f - lx;
                float w11 = hy * hx, w12 = hy * lx;
                float w21 = ly * hx, w22 = ly * lx;

                // Issue all 4 corner LDG.128s first (MLP=4), then convert+fma.
                uint4 u11 = *(const uint4*)(fb + (size_t)(ylo * Wc + xlo) * Cc);
                uint4 u12 = *(const uint4*)(fb + (size_t)(ylo * Wc + xhi) * Cc);
                uint4 u21 = *(const uint4*)(fb + (size_t)(yhi * Wc + xlo) * Cc);
                uint4 u22 = *(const uint4*)(fb + (size_t)(yhi * Wc + xhi) * Cc);

                float2 f;
                #define ACC(U, W) { \
                    const __half2* hp = (const __half2*)&(U); \
                    f = __half22float2(hp[0]); a0 = fmaf(W, f.x, a0); a1 = fmaf(W, f.y, a1); \
                    f = __half22float2(hp[1]); a2 = fmaf(W, f.x, a2); a3 = fmaf(W, f.y, a3); \
                    f = __half22float2(hp[2]); a4 = fmaf(W, f.x, a4); a5 = fmaf(W, f.y, a5); \
                    f = __half22float2(hp[3]); a6 = fmaf(W, f.x, a6); a7 = fmaf(W, f.y, a7); }
                ACC(u11, w11)
                ACC(u12, w12)
                ACC(u21, w21)
                ACC(u22, w22)
                #undef ACC
            }
        }

        float* sp = s + bin * CPAD + c8 * 8;
        *(float4*)(sp)     = make_float4(a0*0.25f, a1*0.25f, a2*0.25f, a3*0.25f);
        *(float4*)(sp + 4) = make_float4(a4*0.25f, a5*0.25f, a6*0.25f, a7*0.25f);
    }
    __syncthreads();

    // Coalesced copy-out: out[r][c][ph][pw]; this block's 128*49 floats contiguous.
    float* ob = out + (size_t)r * (Cc * PHp * PWp) + (size_t)half * 128 * PHp * PWp;
    #pragma unroll 4
    for (int i = tid; i < 128 * PHp * PWp; i += 256) {
        int c = i / (PHp * PWp);
        int bin = i - c * (PHp * PWp);
        ob[i] = s[bin * CPAD + c];
    }
}

extern "C" void kernel_launch(void* const* d_in, const int* in_sizes, int n_in,
                              void* d_out, int out_size)
{
    const float* feat = (const float*)d_in[0];
    const float* rois = (const float*)d_in[1];
    float* out = (float*)d_out;

    dim3 tg(HWc / 32, Cc / 64, Bc);        // 475 x 4 x 2
    dim3 tb(32, 8, 1);
    transpose_kernel<<<tg, tb>>>(feat);

    roialign_nhwc_kernel<<<Rc * 2, 256>>>(rois, out);
}

// round 6
// speedup vs baseline: 1.4618x; 1.0314x over previous
#include <cuda_runtime.h>
#include <cuda_fp16.h>

#define PHp 7
#define PWp 7
#define SRs 2
#define SCALEc 0.0625f
#define Bc 2
#define Cc 256
#define Hc 100
#define Wc 152
#define Rc 1024
#define HWc (Hc * Wc)          // 15200

// NHWC fp16 scratch: [B][H*W][C] halfs = 15.6 MB
__device__ __half g_nhwc[(size_t)Bc * HWc * Cc];

// ---------------- Phase 1: NCHW fp32 -> NHWC fp16 ----------------
__global__ void __launch_bounds__(256) transpose_kernel(const float* __restrict__ in)
{
    __shared__ float tile[64][33];
    int s0 = blockIdx.x * 32;           // HW tile (475 exact)
    int c0 = blockIdx.y * 64;           // C tile (4 exact)
    int b  = blockIdx.z;

    const float* ib = in + (size_t)b * Cc * HWc;
    __half* ob = g_nhwc + (size_t)b * HWc * Cc;

    int s = s0 + threadIdx.x;
    #pragma unroll
    for (int j = threadIdx.y; j < 64; j += 8)
        tile[j][threadIdx.x] = ib[(size_t)(c0 + j) * HWc + s];
    __syncthreads();

    int tx = threadIdx.x;
    #pragma unroll
    for (int j = threadIdx.y; j < 32; j += 8) {
        __half2 v = __floats2half2_rn(tile[2 * tx][j], tile[2 * tx + 1][j]);
        *(__half2*)(ob + (size_t)(s0 + j) * Cc + c0 + 2 * tx) = v;
    }
}

// ---------------- Phase 2: RoIAlign on NHWC fp16 ----------------
// One block per (roi, channel-half). 256 threads:
//   c8 = tid & 15  -> lane's 8-channel group (LDG.128 = 8 fp16 channels)
//   bs = tid >> 4  -> 16 parallel bin streams over 49 bins
// Subsample records (offsets + half2 weights, 0.25 & validity folded in) are
// precomputed once per block into smem and broadcast-read in the main loop.
#define CPAD 132
#define NSS  (PHp * PWp * SRs * SRs)    // 196 subsample records

__global__ void __launch_bounds__(256) roialign_nhwc_kernel(
    const float* __restrict__ rois,
    float* __restrict__ out)
{
    __shared__ float s[PHp * PWp * CPAD];   // 25,872 B output staging
    __shared__ int4  ridx[NSS];             // 4 byte-offsets per subsample
    __shared__ uint4 rwgt[NSS];             // 4 duplicated-half2 weights

    int r    = blockIdx.x >> 1;
    int half = blockIdx.x & 1;
    int tid  = threadIdx.x;
    int c8   = tid & 15;
    int bs   = tid >> 4;

    const float* roi = rois + r * 5;
    int   b   = (int)roi[0];

    // ---- precompute: one subsample record per thread (tid < 196) ----
    if (tid < NSS) {
        float rsw = roi[1] * SCALEc;
        float rsh = roi[2] * SCALEc;
        float roi_w = fmaxf(roi[3] * SCALEc - rsw, 1.0f);
        float roi_h = fmaxf(roi[4] * SCALEc - rsh, 1.0f);
        float bin_h = roi_h * (1.0f / PHp);
        float bin_w = roi_w * (1.0f / PWp);

        int bin = tid >> 2;
        int ss  = tid & 3;
        int ph = bin / PWp, pw = bin - ph * PWp;
        int iy = ss >> 1,  ix = ss & 1;

        float y = rsh + ((float)ph + ((float)iy + 0.5f) * 0.5f) * bin_h;
        float x = rsw + ((float)pw + ((float)ix + 0.5f) * 0.5f) * bin_w;

        bool valid = (y >= -1.0f) && (y <= (float)Hc) &&
                     (x >= -1.0f) && (x <= (float)Wc);

        float yc = fminf(fmaxf(y, 0.0f), (float)(Hc - 1));
        float xc = fminf(fmaxf(x, 0.0f), (float)(Wc - 1));
        int ylo = (int)floorf(yc);
        int xlo = (int)floorf(xc);
        int yhi = min(ylo + 1, Hc - 1);
        int xhi = min(xlo + 1, Wc - 1);
        float ly = yc - (float)ylo;
        float lx = xc - (float)xlo;
        float hy = 1.0f - ly, hx = 1.0f - lx;

        float sc = valid ? 0.25f : 0.0f;           // fold subsample avg + validity
        float w11 = hy * hx * sc, w12 = hy * lx * sc;
        float w21 = ly * hx * sc, w22 = ly * lx * sc;

        // byte offsets into NHWC (row stride Cc*2 = 512 B)
        ridx[tid] = make_int4((ylo * Wc + xlo) * (Cc * 2),
                              (ylo * Wc + xhi) * (Cc * 2),
                              (yhi * Wc + xlo) * (Cc * 2),
                              (yhi * Wc + xhi) * (Cc * 2));
        __half2 h11 = __floats2half2_rn(w11, w11);
        __half2 h12 = __floats2half2_rn(w12, w12);
        __half2 h21 = __floats2half2_rn(w21, w21);
        __half2 h22 = __floats2half2_rn(w22, w22);
        rwgt[tid] = make_uint4(*(unsigned*)&h11, *(unsigned*)&h12,
                               *(unsigned*)&h21, *(unsigned*)&h22);
    }
    __syncthreads();

    const char* fbb = (const char*)(g_nhwc + (size_t)b * HWc * Cc
                                    + (half * 128 + c8 * 8));

    for (int bin = bs; bin < PHp * PWp; bin += 16) {
        float a0=0.f,a1=0.f,a2=0.f,a3=0.f,a4=0.f,a5=0.f,a6=0.f,a7=0.f;

        #pragma unroll
        for (int ss = 0; ss < 4; ss++) {
            int4  id = ridx[bin * 4 + ss];
            uint4 wv = rwgt[bin * 4 + ss];

            uint4 u11 = *(const uint4*)(fbb + id.x);
            uint4 u12 = *(const uint4*)(fbb + id.y);
            uint4 u21 = *(const uint4*)(fbb + id.z);
            uint4 u22 = *(const uint4*)(fbb + id.w);

            __half2 w11 = *(__half2*)&wv.x;
            __half2 w12 = *(__half2*)&wv.y;
            __half2 w21 = *(__half2*)&wv.z;
            __half2 w22 = *(__half2*)&wv.w;

            const __half2* c11 = (const __half2*)&u11;
            const __half2* c12 = (const __half2*)&u12;
            const __half2* c21 = (const __half2*)&u21;
            const __half2* c22 = (const __half2*)&u22;

            float2 f;
            #define SUB(J, AA, AB) { \
                __half2 sub = __hfma2(w11, c11[J], __hfma2(w12, c12[J], \
                              __hfma2(w21, c21[J], __hmul2(w22, c22[J])))); \
                f = __half22float2(sub); AA += f.x; AB += f.y; }
            SUB(0, a0, a1)
            SUB(1, a2, a3)
            SUB(2, a4, a5)
            SUB(3, a6, a7)
            #undef SUB
        }

        float* sp = s + bin * CPAD + c8 * 8;
        *(float4*)(sp)     = make_float4(a0, a1, a2, a3);
        *(float4*)(sp + 4) = make_float4(a4, a5, a6, a7);
    }
    __syncthreads();

    // Coalesced copy-out: out[r][c][ph][pw]; this block's 128*49 floats contiguous.
    float* ob = out + (size_t)r * (Cc * PHp * PWp) + (size_t)half * 128 * PHp * PWp;
    #pragma unroll 4
    for (int i = tid; i < 128 * PHp * PWp; i += 256) {
        int c = i / (PHp * PWp);
        int bin = i - c * (PHp * PWp);
        ob[i] = s[bin * CPAD + c];
    }
}

extern "C" void kernel_launch(void* const* d_in, const int* in_sizes, int n_in,
                              void* d_out, int out_size)
{
    const float* feat = (const float*)d_in[0];
    const float* rois = (const float*)d_in[1];
    float* out = (float*)d_out;

    dim3 tg(HWc / 32, Cc / 64, Bc);        // 475 x 4 x 2
    dim3 tb(32, 8, 1);
    transpose_kernel<<<tg, tb>>>(feat);

    roialign_nhwc_kernel<<<Rc * 2, 256>>>(rois, out);
}